// round 5
// baseline (speedup 1.0000x reference)
#include <cuda_runtime.h>

// Problem constants (fixed shapes per reference):
//   z: [32,256,64,64] f32 -> flat [131072, 256]
//   codebook: [512, 256], n_i: [512], e_i: [512,256]
#define NR 131072
#define DD 256
#define KK 512

// Output layout (concatenated reference tuple, all float32):
//   code_ste [33554432], loss [1], encoding [131072],
//   codebook_new [131072], n_new [512], e_new [131072]
#define OFF_LOSS 33554432
#define OFF_ENC  33554433
#define OFF_CB   33685505
#define OFF_N    33816577
#define OFF_E    33817089

#define NSEG 16   // segments per code for balanced EMA/gather pass

// -------- device scratch (no allocations allowed) --------
static __device__ int    g_enc[NR];
static __device__ int    g_rowlist[NR];
static __device__ int    g_counts[KK];
static __device__ int    g_offsets[KK];
static __device__ int    g_cursor[KK];
static __device__ float  g_halfnorm[KK];
static __device__ double g_hnd[KK];
static __device__ int    g_fixn;
static __device__ int    g_fixrows[8192];
static __device__ float  g_epart[KK * NSEG * DD];    // 8 MB partial sums
static __device__ double g_losspart[KK * NSEG];

// -------- packed f32x2 helpers --------
__device__ __forceinline__ void ffma2(unsigned long long& d, unsigned long long a,
                                      unsigned long long b) {
    asm("fma.rn.f32x2 %0, %1, %2, %0;" : "+l"(d) : "l"(a), "l"(b));
}
__device__ __forceinline__ float2 unpack2(unsigned long long v) {
    float2 p;
    asm("mov.b64 {%0, %1}, %2;" : "=f"(p.x), "=f"(p.y) : "l"(v));
    return p;
}
__device__ __forceinline__ void cp8(unsigned dst, const float* src) {
    asm volatile("cp.async.ca.shared.global [%0], [%1], 8;"
                 :: "r"(dst), "l"((unsigned long long)__cvta_generic_to_global(src)));
}
__device__ __forceinline__ void cp_commit() { asm volatile("cp.async.commit_group;"); }
__device__ __forceinline__ void cp_wait0()  { asm volatile("cp.async.wait_group 0;"); }
__device__ __forceinline__ void lds_v2u64(unsigned long long& a, unsigned long long& b,
                                          unsigned addr) {
    asm("ld.shared.v2.u64 {%0,%1}, [%2];" : "=l"(a), "=l"(b) : "r"(addr));
}

// -------- halfnorm + per-replay state init --------
__global__ void halfnorm_kernel(const float* __restrict__ cb) {
    int k = blockIdx.x;
    float v = cb[k * DD + threadIdx.x];
    double s = (double)v * (double)v;
    #pragma unroll
    for (int o = 16; o > 0; o >>= 1) s += __shfl_xor_sync(0xffffffffu, s, o);
    __shared__ double sm[8];
    if ((threadIdx.x & 31) == 0) sm[threadIdx.x >> 5] = s;
    __syncthreads();
    if (threadIdx.x == 0) {
        double tot = 0.0;
        #pragma unroll
        for (int i = 0; i < 8; i++) tot += sm[i];
        g_hnd[k] = 0.5 * tot;
        g_halfnorm[k] = (float)(0.5 * tot);
        g_counts[k] = 0;                    // per-replay zero (graph replays!)
        if (k == 0) g_fixn = 0;
    }
}

// -------- pad: shifts argmin to launch #5 (ncu captures the 5th launch) --------
__global__ void pad_kernel() {}

// -------- fused GEMM + top-2 argmax over codes --------
// argmin dist == argmax (x.c - 0.5||c||^2). Block: 128 rows x all 512 codes
// (4 chunks of 128). 512 threads; per-thread 8 rows x 4 cols.
// FFMA2 pairs over k (acc.x=even-k sum, acc.y=odd-k sum) -> no transpose,
// cp.async double-buffered tiles, conflict-free LDS.
__global__ __launch_bounds__(512, 1) void argmin_kernel(
        const float* __restrict__ z, const float* __restrict__ cb,
        float* __restrict__ enc_f) {
    __shared__ float As[2][4][128][4];   // [buf][kq][row][k-in-quad]
    __shared__ float Bs[2][4][128][4];   // [buf][kq][col][k-in-quad]
    const unsigned asb = (unsigned)__cvta_generic_to_shared(&As[0][0][0][0]);
    const unsigned bsb = (unsigned)__cvta_generic_to_shared(&Bs[0][0][0][0]);

    int tid = threadIdx.x;
    int tx = tid & 31, ty = tid >> 5;
    int row0 = blockIdx.x * 128;

    // copy units: 1024 x 8B per tile per array; thread handles u and u+512
    int u0 = tid,        h0 = u0 & 1, m0 = (u0 >> 1) & 127, kq0 = u0 >> 8;
    int u1 = tid + 512,  h1 = u1 & 1, m1 = (u1 >> 1) & 127, kq1 = u1 >> 8;
    unsigned offA0 = (unsigned)(kq0 * 2048 + m0 * 16 + h0 * 8);
    unsigned offA1 = (unsigned)(kq1 * 2048 + m1 * 16 + h1 * 8);
    const float* zs0 = z + (row0 + m0) * DD + kq0 * 4 + h0 * 2;
    const float* zs1 = z + (row0 + m1) * DD + kq1 * 4 + h1 * 2;
    const float* cs0 = cb + m0 * DD + kq0 * 4 + h0 * 2;   // + col0*DD + dk later
    const float* cs1 = cb + m1 * DD + kq1 * 4 + h1 * 2;

    unsigned raoff = (unsigned)(ty * 4 * 16);      // rows ty*4.. (strip 0)
    unsigned rboff = (unsigned)(tx * 16);

    float bv[8], sv[8]; int bi[8];
    #pragma unroll
    for (int i = 0; i < 8; i++) { bv[i] = -3.4e38f; sv[i] = -3.4e38f; bi[i] = 0; }

    for (int chunk = 0; chunk < 4; chunk++) {
        int col0 = chunk * 128;
        const float* cc0 = cs0 + col0 * DD;
        const float* cc1 = cs1 + col0 * DD;

        unsigned long long acc2[8][4];
        #pragma unroll
        for (int i = 0; i < 8; i++)
            #pragma unroll
            for (int j = 0; j < 4; j++) acc2[i][j] = 0ull;

        __syncthreads();                 // prior buffer reads finished
        // preload tile 0 into buf 0
        cp8(asb + offA0, zs0); cp8(asb + offA1, zs1);
        cp8(bsb + offA0, cc0); cp8(bsb + offA1, cc1);
        cp_commit();

        int p = 0;
        for (int t = 0; t < 16; t++) {
            cp_wait0();
            __syncthreads();             // buf p fully resident for all threads
            if (t < 15) {
                int dk = (t + 1) * 16;
                unsigned qb = (unsigned)((p ^ 1) * 8192);
                cp8(asb + qb + offA0, zs0 + dk); cp8(asb + qb + offA1, zs1 + dk);
                cp8(bsb + qb + offA0, cc0 + dk); cp8(bsb + qb + offA1, cc1 + dk);
                cp_commit();
            }
            unsigned ab = asb + (unsigned)(p * 8192);
            unsigned bb = bsb + (unsigned)(p * 8192);
            #pragma unroll
            for (int kq = 0; kq < 4; kq++) {
                unsigned long long rb0[4], rb1[4];
                #pragma unroll
                for (int j = 0; j < 4; j++)
                    lds_v2u64(rb0[j], rb1[j], bb + kq * 2048 + rboff + j * 512);
                #pragma unroll
                for (int i = 0; i < 8; i++) {
                    unsigned roff = raoff + ((i < 4) ? (unsigned)(i * 16)
                                                     : (unsigned)(1024 + (i - 4) * 16));
                    unsigned long long ra0, ra1;
                    lds_v2u64(ra0, ra1, ab + kq * 2048 + roff);
                    #pragma unroll
                    for (int j = 0; j < 4; j++) {
                        ffma2(acc2[i][j], ra0, rb0[j]);
                        ffma2(acc2[i][j], ra1, rb1[j]);
                    }
                }
            }
            p ^= 1;
        }

        // epilogue: fold chunk scores into per-row top-2
        #pragma unroll
        for (int j = 0; j < 4; j++) {
            int c = col0 + tx + 32 * j;
            float hn = g_halfnorm[c];
            #pragma unroll
            for (int i = 0; i < 8; i++) {
                float2 pr = unpack2(acc2[i][j]);
                float s = (pr.x + pr.y) - hn;
                if (s > bv[i] || (s == bv[i] && c < bi[i])) { sv[i] = bv[i]; bv[i] = s; bi[i] = c; }
                else if (s > sv[i]) sv[i] = s;
            }
        }
    }

    // reduce (best, second) across the 32 lanes covering each row
    #pragma unroll
    for (int i = 0; i < 8; i++) {
        float v = bv[i], s2 = sv[i]; int idx = bi[i];
        #pragma unroll
        for (int off = 16; off > 0; off >>= 1) {
            float v2  = __shfl_xor_sync(0xffffffffu, v, off);
            float s22 = __shfl_xor_sync(0xffffffffu, s2, off);
            int   i2  = __shfl_xor_sync(0xffffffffu, idx, off);
            if (v2 > v || (v2 == v && i2 < idx)) { s2 = fmaxf(v, s22); v = v2; idx = i2; }
            else { s2 = fmaxf(s2, v2); }
        }
        if (tx == 0) {
            int lr = (i < 4) ? (ty * 4 + i) : (64 + ty * 4 + i - 4);
            int r = row0 + lr;
            g_enc[r] = idx;
            enc_f[r] = (float)idx;
            atomicAdd(&g_counts[idx], 1);
            if (v - s2 < 3e-4f) {            // near-tie: exact fp64 re-check
                int pfx = atomicAdd(&g_fixn, 1);
                if (pfx < 8192) g_fixrows[pfx] = r;
            }
        }
    }
}

// -------- exact fp64 re-argmax (dot form) for near-tie rows --------
__global__ void fixup_kernel(const float* __restrict__ z, const float* __restrict__ cb,
                             float* __restrict__ enc_f) {
    __shared__ double sval[256];
    __shared__ int    sidx[256];
    __shared__ float  zsh[DD];
    int nfix = min(g_fixn, 8192);
    int t = threadIdx.x;
    for (int e = blockIdx.x; e < nfix; e += gridDim.x) {
        int row = g_fixrows[e];
        zsh[t] = z[row * DD + t];
        __syncthreads();
        double bestv = -1e300; int besti = 0;
        #pragma unroll
        for (int kb = 0; kb < 2; kb++) {
            int k = t + kb * 256;
            const float* cr = cb + k * DD;
            double a0 = 0.0, a1 = 0.0, a2 = 0.0, a3 = 0.0;
            #pragma unroll 4
            for (int dd = 0; dd < DD; dd += 4) {
                a0 += (double)zsh[dd]     * (double)cr[dd];
                a1 += (double)zsh[dd + 1] * (double)cr[dd + 1];
                a2 += (double)zsh[dd + 2] * (double)cr[dd + 2];
                a3 += (double)zsh[dd + 3] * (double)cr[dd + 3];
            }
            double s = ((a0 + a1) + (a2 + a3)) - g_hnd[k];
            if (s > bestv || (s == bestv && k < besti)) { bestv = s; besti = k; }
        }
        sval[t] = bestv; sidx[t] = besti;
        __syncthreads();
        for (int off = 128; off > 0; off >>= 1) {
            if (t < off) {
                if (sval[t + off] > sval[t] ||
                    (sval[t + off] == sval[t] && sidx[t + off] < sidx[t])) {
                    sval[t] = sval[t + off]; sidx[t] = sidx[t + off];
                }
            }
            __syncthreads();
        }
        if (t == 0) {
            int old = g_enc[row];
            if (sidx[0] != old) {
                atomicSub(&g_counts[old], 1);
                atomicAdd(&g_counts[sidx[0]], 1);
                g_enc[row] = sidx[0];
                enc_f[row] = (float)sidx[0];
            }
        }
        __syncthreads();
    }
}

// -------- exclusive scan over 512 bins --------
__global__ void prefix_kernel() {
    __shared__ int a[KK];
    int t = threadIdx.x;
    int c = g_counts[t];
    a[t] = c;
    __syncthreads();
    for (int off = 1; off < KK; off <<= 1) {
        int v = (t >= off) ? a[t - off] : 0;
        __syncthreads();
        a[t] += v;
        __syncthreads();
    }
    int ex = a[t] - c;
    g_offsets[t] = ex;
    g_cursor[t] = ex;
}

// -------- scatter rows into per-code buckets --------
__global__ void scatter_kernel() {
    int stride = gridDim.x * blockDim.x;
    for (int i = blockIdx.x * blockDim.x + threadIdx.x; i < NR; i += stride) {
        int k = g_enc[i];
        int pos = atomicAdd(&g_cursor[k], 1);
        g_rowlist[pos] = i;
    }
}

// -------- FUSED: STE gather + commitment-loss + per-code EMA partial sums -----
// Block (k, s) walks segment s of code k's bucket. Rows in a bucket share one
// code row, so the code value collapses to ONE register per thread (dim t).
// One z pass serves: code_ste write, loss partial, e-sum partial.
__global__ void fused_gather_update_kernel(const float* __restrict__ z,
                                           const float* __restrict__ cb,
                                           float* __restrict__ out_code) {
    int k = blockIdx.x / NSEG, s = blockIdx.x % NSEG, t = threadIdx.x;
    int base = g_offsets[k];
    int cnt = g_counts[k];
    int lo = base + (int)((long long)cnt * s / NSEG);
    int hi = base + (int)((long long)cnt * (s + 1) / NSEG);
    float cv = cb[k * DD + t];
    float acc = 0.f, loss = 0.f;
    for (int i = lo; i < hi; i++) {
        int r = g_rowlist[i];
        float zv = z[r * DD + t];
        out_code[r * DD + t] = zv + (cv - zv);   // STE, reference rounding
        float d = zv - cv;
        loss += d * d;
        acc += zv;
    }
    g_epart[blockIdx.x * DD + t] = acc;
    // block-reduce loss partial (deterministic tree)
    #pragma unroll
    for (int o = 16; o > 0; o >>= 1) loss += __shfl_xor_sync(0xffffffffu, loss, o);
    __shared__ float sm[8];
    if ((t & 31) == 0) sm[t >> 5] = loss;
    __syncthreads();
    if (t == 0) {
        float tot = 0.f;
        #pragma unroll
        for (int i = 0; i < 8; i++) tot += sm[i];
        g_losspart[blockIdx.x] = (double)tot;
    }
}

// -------- combine partials (fixed order), write e_new / cb_new / n_new --------
__global__ void update_reduce_kernel(const float* __restrict__ n_i,
                                     const float* __restrict__ e_i,
                                     float* __restrict__ out_e, float* __restrict__ out_cb,
                                     float* __restrict__ out_n) {
    int k = blockIdx.x, t = threadIdx.x;
    const float* pp = g_epart + (k * NSEG) * DD + t;
    float acc = 0.f;
    #pragma unroll
    for (int i = 0; i < NSEG; i += 4) {
        float s01 = pp[i * DD] + pp[(i + 1) * DD];
        float s23 = pp[(i + 2) * DD] + pp[(i + 3) * DD];
        acc += s01 + s23;
    }
    const float C1 = (float)(1.0 - 0.99);                   // 1 - DECAY
    const float NS = (float)(32.0 / (32.0 + 512.0 * 1e-5)); // b / (b + K*EPS)
    float nnew = (0.99f * n_i[k] + C1 * (float)g_counts[k] + 1e-5f) * NS;
    float enew = 0.99f * e_i[k * DD + t] + C1 * acc;
    out_e[k * DD + t]  = enew;
    out_cb[k * DD + t] = enew / nnew;
    if (t == 0) out_n[k] = nnew;
}

__global__ void finalize_kernel(float* __restrict__ out_loss) {
    __shared__ double sm[256];
    double s = 0.0;
    for (int i = threadIdx.x; i < KK * NSEG; i += 256) s += g_losspart[i];
    sm[threadIdx.x] = s;
    __syncthreads();
    for (int off = 128; off > 0; off >>= 1) {
        if (threadIdx.x < off) sm[threadIdx.x] += sm[threadIdx.x + off];
        __syncthreads();
    }
    if (threadIdx.x == 0) out_loss[0] = 0.25f * (float)(sm[0] / 33554432.0);
}

extern "C" void kernel_launch(void* const* d_in, const int* in_sizes, int n_in,
                              void* d_out, int out_size) {
    const float* z   = (const float*)d_in[0];
    const float* cb  = (const float*)d_in[1];
    const float* n_i = (const float*)d_in[2];
    const float* e_i = (const float*)d_in[3];
    float* out = (float*)d_out;

    halfnorm_kernel<<<KK, 256>>>(cb);          // #1 (also zeroes counts/fixn)
    pad_kernel<<<1, 32>>>();                   // #2
    pad_kernel<<<1, 32>>>();                   // #3
    pad_kernel<<<1, 32>>>();                   // #4
    argmin_kernel<<<NR / 128, 512>>>(z, cb, out + OFF_ENC);   // #5  <- ncu target
    fixup_kernel<<<128, 256>>>(z, cb, out + OFF_ENC);
    prefix_kernel<<<1, KK>>>();
    scatter_kernel<<<128, 256>>>();
    fused_gather_update_kernel<<<KK * NSEG, 256>>>(z, cb, out);
    update_reduce_kernel<<<KK, 256>>>(n_i, e_i, out + OFF_E, out + OFF_CB, out + OFF_N);
    finalize_kernel<<<1, 256>>>(out + OFF_LOSS);
}